// round 14
// baseline (speedup 1.0000x reference)
#include <cuda_runtime.h>
#include <cuda_bf16.h>
#include <math.h>
#include <stdint.h>

// Shapes (fixed)
#define D_  1024
#define B_  128
#define T_  256

#define KSTAGE  64                    // k per stage
#define NSTAGES (D_ / KSTAGE)         // 16
#define A_STAGE 32768                 // A: 128 rows x 64 k, hi 16K + lo 16K
#define NBUF    3
#define A_PIPE  (NBUF * A_STAGE)      // 98304
#define B_RES   A_PIPE                // B resident: 16 stages x (4K hi + 4K lo)
#define SMEM_DYN (A_PIPE + 16 * 8192) // 229376 = 224 KB, 1 CTA/SM

#define NCTA    128                   // one n-tile (N=32) per CTA, M=128
#define NTHREADS 512                  // 16 warps = 4 m-warps x 4 kq-groups
#define CREG    18432u                // combine region stride (128*36*4)

// Device scratch (allocation-free)
__device__ unsigned short g_WcThi[4 * D_ * D_];   // combined W^T hi  [n][k]
__device__ unsigned short g_WcTlo[4 * D_ * D_];
__device__ unsigned short g_W1Thi[4 * D_ * D_];   // step-1 W^T hi
__device__ unsigned short g_W1Tlo[4 * D_ * D_];
__device__ unsigned short g_hHi[2][B_ * D_];      // h split ping-pong
__device__ unsigned short g_hLo[2][B_ * D_];
__device__ unsigned       g_bar;                  // grid barrier counter

// ---------------------------------------------------------------------------
// PTX helpers (plain sm_80+ features only)
// ---------------------------------------------------------------------------
__device__ __forceinline__ uint32_t s2u(const void* p) {
    uint32_t a;
    asm("{ .reg .u64 t; cvta.to.shared.u64 t, %1; cvt.u32.u64 %0, t; }"
        : "=r"(a) : "l"(p));
    return a;
}
__device__ __forceinline__ void cpasync16(uint32_t dst, const void* src) {
    asm volatile("cp.async.cg.shared.global [%0], [%1], 16;" :: "r"(dst), "l"(src));
}
__device__ __forceinline__ void cp_commit() {
    asm volatile("cp.async.commit_group;" ::: "memory");
}
template <int N> __device__ __forceinline__ void cp_wait() {
    asm volatile("cp.async.wait_group %0;" :: "n"(N) : "memory");
}
__device__ __forceinline__ void ldsm4(uint32_t* r, uint32_t addr) {
    asm volatile("ldmatrix.sync.aligned.m8n8.x4.shared.b16 {%0,%1,%2,%3}, [%4];"
        : "=r"(r[0]), "=r"(r[1]), "=r"(r[2]), "=r"(r[3]) : "r"(addr));
}
__device__ __forceinline__ void mma_bf16(float* c, const uint32_t* a,
                                         uint32_t b0, uint32_t b1) {
    asm volatile("mma.sync.aligned.m16n8k16.row.col.f32.bf16.bf16.f32 "
        "{%0,%1,%2,%3}, {%4,%5,%6,%7}, {%8,%9}, {%0,%1,%2,%3};"
        : "+f"(c[0]), "+f"(c[1]), "+f"(c[2]), "+f"(c[3])
        : "r"(a[0]), "r"(a[1]), "r"(a[2]), "r"(a[3]), "r"(b0), "r"(b1));
}
__device__ __forceinline__ uint32_t sw128(uint32_t off) {
    return off ^ ((off >> 3) & 0x70);
}

// ---------------------------------------------------------------------------
// Merged prologue: weights transform + x0 split + barrier reset.
// ---------------------------------------------------------------------------
__global__ void prep_all(const float* __restrict__ Wk,
                         const float* __restrict__ Wr,
                         const float* __restrict__ x,
                         float* __restrict__ out) {
    int i = blockIdx.x * blockDim.x + threadIdx.x;
    {   // ---- weights: [n][k] transposed, gates {Wz+Rz, Wr+Rr, Wh, Rh} ----
        int n  = i >> 7;
        int k0 = (i & 127) * 8;
        int d = n >> 2, g = n & 3;
        long o = (long)n * D_ + k0;
        #pragma unroll
        for (int j = 0; j < 8; j++) {
            long src = (long)(k0 + j) * (3 * D_) + (long)g * D_ + d;
            float wc, w1;
            if (g == 3) {
                float rh = Wr[(long)(k0 + j) * (3 * D_) + 2 * D_ + d];
                wc = rh; w1 = 0.f;
            } else {
                float a = Wk[src];
                float b = Wr[src];
                w1 = a;
                wc = (g == 2) ? a : (a + b);
            }
            __nv_bfloat16 ch = __float2bfloat16(wc);
            __nv_bfloat16 cl = __float2bfloat16(wc - __bfloat162float(ch));
            __nv_bfloat16 oh = __float2bfloat16(w1);
            __nv_bfloat16 ol = __float2bfloat16(w1 - __bfloat162float(oh));
            g_WcThi[o + j] = __bfloat16_as_ushort(ch);
            g_WcTlo[o + j] = __bfloat16_as_ushort(cl);
            g_W1Thi[o + j] = __bfloat16_as_ushort(oh);
            g_W1Tlo[o + j] = __bfloat16_as_ushort(ol);
        }
    }
    if (i < B_ * D_) {   // ---- x0: out[:,0,:] = x0; split into h buf 0 ----
        if (i == 0) g_bar = 0u;
        int b = i >> 10, d = i & (D_ - 1);
        float v = x[(long)b * D_ + d];
        out[(long)b * (T_ * D_) + d] = v;
        __nv_bfloat16 hi = __float2bfloat16(v);
        g_hHi[0][i] = __bfloat16_as_ushort(hi);
        g_hLo[0][i] = __bfloat16_as_ushort(
            __float2bfloat16(v - __bfloat162float(hi)));
    }
}

// ---------------------------------------------------------------------------
// Loaders
// ---------------------------------------------------------------------------
// Per-warp A slab: warp (wm,wk) loads rows [wm*32,+32) x k-bytes [wk*32,+32)
// of one stage (hi+lo), matching exactly the region its own ldsm reads.
// 4 cp.async per lane.
__device__ __forceinline__ void load_A_warp(
    uint32_t st, int k0,
    const unsigned short* Ahi, const unsigned short* Alo,
    int wm, int wk, int lane)
{
    #pragma unroll
    for (int t = 0; t < 2; t++) {
        int row = wm * 32 + t * 16 + (lane >> 1);
        int ch  = wk * 2 + (lane & 1);
        uint32_t sw = sw128((uint32_t)(row * 128 + ch * 16));
        const long ko = (long)k0 + ch * 8;
        cpasync16(st +         sw, Ahi + (long)row * D_ + ko);
        cpasync16(st + 16384 + sw, Alo + (long)row * D_ + ko);
    }
}
// B resident: 16 stages x 32 rows x 64 k, hi+lo (128 KB), all 512 threads.
__device__ __forceinline__ void load_B_res(
    uint32_t sbase, const unsigned short* Bhi, const unsigned short* Blo,
    int nrow0, int tid)
{
    #pragma unroll
    for (int t = 0; t < 8; t++) {
        int r   = t * 512 + tid;            // 4096 chunks per half
        int s   = r >> 8;                   // stage
        int rr  = r & 255;
        int row = rr >> 3, ch = rr & 7;
        uint32_t dst = sbase + B_RES + (uint32_t)s * 8192;
        uint32_t sw = sw128((uint32_t)(row * 128 + ch * 16));
        const long ko = (long)s * KSTAGE + ch * 8;
        cpasync16(dst +        sw, Bhi + (long)(nrow0 + row) * D_ + ko);
        cpasync16(dst + 4096 + sw, Blo + (long)(nrow0 + row) * D_ + ko);
    }
}

// ---------------------------------------------------------------------------
// Persistent GRU: 255 steps, grid barrier between steps.
// Grid 128 CTAs (1/SM): CTA tile M=128 x N=32; weights RESIDENT in smem.
// 16 warps = 4 m-warps x 4 kq-groups, warp tile 32x32. BARRIER-FREE
// mainloop: each warp cp.asyncs its private A slab and syncs only with
// __syncwarp; one __syncthreads per step (B visibility at s==0).
// Distributed combine + epilogue (R13).
// ---------------------------------------------------------------------------
extern __shared__ char dsm[];

__global__ __launch_bounds__(NTHREADS, 1)
void gru_persist(const unsigned short* __restrict__ WcHi,
                 const unsigned short* __restrict__ WcLo,
                 const unsigned short* __restrict__ W1Hi,
                 const unsigned short* __restrict__ W1Lo,
                 const float* __restrict__ bias,
                 float* __restrict__ out,
                 unsigned short* __restrict__ hHi,
                 unsigned short* __restrict__ hLo)
{
    const uint32_t sbase = s2u(dsm);
    const int tid  = threadIdx.x;
    const int wid  = tid >> 5, lane = tid & 31;
    const int wk   = wid >> 2;                      // kq-group 0..3
    const int wm   = wid & 3;                       // m-warp (32 rows each)
    const int nb   = blockIdx.x;                    // n-tile (N=32)
    const int nrow0 = nb * 32;

    // per-lane ldmatrix geometry
    const int fr   = (lane & 7) + ((lane >> 3) & 1) * 8;
    const int fch  = (lane >> 4) * 16;
    const uint32_t swz = (uint32_t)(lane & 7) << 4;
    const uint32_t ckq = (uint32_t)(wk * 32 + fch);   // this group's k-quarter

    // distributed-epilogue coordinates: each thread owns (erow, d2..d2+1)
    const int erow = tid >> 2;                      // 0..127
    const int ed0  = (tid & 3) * 2;                 // local d: ed0, ed0+1
    const int dg0  = nb * 8 + ed0;                  // global d base

    float bzv[2], brv[2], bhv[2];
    #pragma unroll
    for (int q = 0; q < 2; q++) {
        bzv[q] = bias[dg0 + q];
        brv[q] = bias[D_ + dg0 + q];
        bhv[q] = bias[2 * D_ + dg0 + q];
    }

    // ---- prime for t = 1: B-resident = W1, A stages 0..1 (per-warp) ----
    const unsigned short* Ahi = hHi;
    const unsigned short* Alo = hLo;
    load_B_res(sbase, W1Hi, W1Lo, nrow0, tid);
    cp_commit();
    load_A_warp(sbase,           0,      Ahi, Alo, wm, wk, lane); cp_commit();
    load_A_warp(sbase + A_STAGE, KSTAGE, Ahi, Alo, wm, wk, lane); cp_commit();

    float hold[2] = {0.f, 0.f};                     // h0 = 0

    for (int t = 1; t < T_; t++) {
        const bool last = (t == T_ - 1);

        float acc[2][4][4];
        #pragma unroll
        for (int i = 0; i < 2; i++)
            #pragma unroll
            for (int j = 0; j < 4; j++)
                #pragma unroll
                for (int q = 0; q < 4; q++) acc[i][j][q] = 0.f;

        int buf = 0;
        for (int s = 0; s < NSTAGES; s++) {
            if (s < NSTAGES - 1) cp_wait<1>();
            else                 cp_wait<0>();
            __syncwarp();
            if (s == 0) __syncthreads();   // B-resident visibility (1/step)

            const uint32_t aHi = sbase + (uint32_t)buf * A_STAGE;
            const uint32_t aLo = aHi + 16384;
            const uint32_t bHi = sbase + B_RES + (uint32_t)s * 8192;
            const uint32_t bLo = bHi + 4096;

            const uint32_t c = ckq ^ swz;
            uint32_t ah[2][4], al[2][4], bh[2][4], bl[2][4];
            #pragma unroll
            for (int mt = 0; mt < 2; mt++) {
                uint32_t ro = (uint32_t)((wm * 32 + mt * 16 + fr) * 128) + c;
                ldsm4(ah[mt], aHi + ro);
                ldsm4(al[mt], aLo + ro);
            }
            #pragma unroll
            for (int np = 0; np < 2; np++) {
                uint32_t ro = (uint32_t)((np * 16 + fr) * 128) + c;
                ldsm4(bh[np], bHi + ro);
                ldsm4(bl[np], bLo + ro);
            }

            // refill stage s+2 into this warp's slab of buf (s+2)%3
            if (s + 2 < NSTAGES) {
                int nxt = buf + 2; if (nxt >= NBUF) nxt -= NBUF;
                load_A_warp(sbase + (uint32_t)nxt * A_STAGE, (s + 2) * KSTAGE,
                            Ahi, Alo, wm, wk, lane);
                cp_commit();
            }

            #pragma unroll
            for (int mt = 0; mt < 2; mt++)
                #pragma unroll
                for (int nt = 0; nt < 4; nt++) {
                    const int np = nt >> 1, j = nt & 1;
                    mma_bf16(acc[mt][nt], ah[mt], bh[np][j], bh[np][j + 2]);
                    mma_bf16(acc[mt][nt], ah[mt], bl[np][j], bl[np][j + 2]);
                    mma_bf16(acc[mt][nt], al[mt], bh[np][j], bh[np][j + 2]);
                }
            buf = buf + 1; if (buf == NBUF) buf = 0;
        }

        // -------- all groups dump partials to smem (A-pipe area idle) -----
        __syncthreads();                       // all warps done with bufs
        {
            const uint32_t comb = sbase + (uint32_t)wk * CREG;
            #pragma unroll
            for (int mt = 0; mt < 2; mt++)
                #pragma unroll
                for (int nt = 0; nt < 4; nt++) {
                    int r0 = wm * 32 + mt * 16 + (lane >> 2);
                    int c0 = nt * 8 + 2 * (lane & 3);
                    uint32_t ad = comb + (uint32_t)((r0 * 36 + c0) << 2);
                    asm volatile("st.shared.v2.f32 [%0], {%1,%2};"
                                 :: "r"(ad), "f"(acc[mt][nt][0]), "f"(acc[mt][nt][1]));
                    asm volatile("st.shared.v2.f32 [%0], {%1,%2};"
                                 :: "r"(ad + 8 * 36 * 4),
                                    "f"(acc[mt][nt][2]), "f"(acc[mt][nt][3]));
                }
        }
        __syncthreads();

        // -------- distributed combine + GRU gates: 2 outputs / thread -----
        unsigned short* nhi = hHi + (size_t)(t & 1) * B_ * D_;
        unsigned short* nlo = hLo + (size_t)(t & 1) * B_ * D_;
        {
            float hv[2];
            #pragma unroll
            for (int q = 0; q < 2; q++) {
                const int dl = ed0 + q;
                const uint32_t off = (uint32_t)((erow * 36 + dl * 4) << 2);
                float az = 0.f, ar = 0.f, ahs = 0.f, ags = 0.f;
                #pragma unroll
                for (int gq = 0; gq < 4; gq++) {
                    float p0, p1, p2, p3;
                    asm volatile("ld.shared.v4.f32 {%0,%1,%2,%3}, [%4];"
                                 : "=f"(p0), "=f"(p1), "=f"(p2), "=f"(p3)
                                 : "r"(sbase + (uint32_t)gq * CREG + off));
                    az += p0; ar += p1; ahs += p2; ags += p3;
                }
                float z  = 1.f / (1.f + __expf(-(az + bzv[q])));
                float rr = 1.f / (1.f + __expf(-(ar + brv[q])));
                float xc = ahs + bhv[q] + rr * ags;
                float e  = __expf(-2.f * xc);
                float cand = (1.f - e) / (1.f + e);
                float h = z * hold[q] + (1.f - z) * cand;
                hold[q] = h;
                hv[q] = h;
            }
            // coalesced stores
            float* po = out + (long)erow * (T_ * D_) + (long)t * D_ + dg0;
            *(float2*)po = make_float2(hv[0], hv[1]);
            __nv_bfloat16 h0 = __float2bfloat16(hv[0]);
            __nv_bfloat16 h1 = __float2bfloat16(hv[1]);
            uint32_t hiw = (uint32_t)__bfloat16_as_ushort(h0)
                         | ((uint32_t)__bfloat16_as_ushort(h1) << 16);
            __nv_bfloat16 l0 = __float2bfloat16(hv[0] - __bfloat162float(h0));
            __nv_bfloat16 l1 = __float2bfloat16(hv[1] - __bfloat162float(h1));
            uint32_t low = (uint32_t)__bfloat16_as_ushort(l0)
                         | ((uint32_t)__bfloat16_as_ushort(l1) << 16);
            *(uint32_t*)(nhi + (long)erow * D_ + dg0) = hiw;
            *(uint32_t*)(nlo + (long)erow * D_ + dg0) = low;
        }

        if (!last) {
            // ---- grid barrier: all h_t writes visible before step t+1 ----
            __threadfence();
            __syncthreads();
            if (tid == 0) {
                atomicAdd(&g_bar, 1u);
                volatile unsigned* vb = &g_bar;
                const unsigned target = (unsigned)NCTA * (unsigned)t;
                while (*vb < target) { }
            }
            __syncthreads();
            __threadfence();

            Ahi = nhi; Alo = nlo;

            // switch resident weights to Wc after step 1
            if (t == 1) {
                load_B_res(sbase, WcHi, WcLo, nrow0, tid);
                cp_commit();
            }
            // A stages 0..1 for next step (per-warp slabs)
            load_A_warp(sbase,           0,      Ahi, Alo, wm, wk, lane); cp_commit();
            load_A_warp(sbase + A_STAGE, KSTAGE, Ahi, Alo, wm, wk, lane); cp_commit();
        }
    }
}

// ---------------------------------------------------------------------------
extern "C" void kernel_launch(void* const* d_in, const int* in_sizes, int n_in,
                              void* d_out, int out_size) {
    const float* x    = (const float*)d_in[0];
    const float* Wk   = (const float*)d_in[1];
    const float* Wr   = (const float*)d_in[2];
    const float* bias = (const float*)d_in[3];
    float* out = (float*)d_out;

    unsigned short *WcHi, *WcLo, *W1Hi, *W1Lo, *hHi, *hLo;
    cudaGetSymbolAddress((void**)&WcHi, g_WcThi);
    cudaGetSymbolAddress((void**)&WcLo, g_WcTlo);
    cudaGetSymbolAddress((void**)&W1Hi, g_W1Thi);
    cudaGetSymbolAddress((void**)&W1Lo, g_W1Tlo);
    cudaGetSymbolAddress((void**)&hHi,  g_hHi);
    cudaGetSymbolAddress((void**)&hLo,  g_hLo);

    cudaFuncSetAttribute(gru_persist,
                         cudaFuncAttributeMaxDynamicSharedMemorySize, SMEM_DYN);

    prep_all<<<2048, 256>>>(Wk, Wr, x, out);   // also resets g_bar

    gru_persist<<<NCTA, NTHREADS, SMEM_DYN>>>(WcHi, WcLo, W1Hi, W1Lo,
                                              bias, out, hHi, hLo);
}

// round 15
// speedup vs baseline: 1.2766x; 1.2766x over previous
#include <cuda_runtime.h>
#include <cuda_fp16.h>
#include <math.h>
#include <stdint.h>

// Shapes (fixed)
#define D_  1024
#define B_  128
#define T_  256

#define KSTAGE  64                    // k per stage
#define NSTAGES (D_ / KSTAGE)         // 16
#define A_STAGE 32768                 // A: 128 rows x 64 k, hi 16K + lo 16K
#define NBUF    3
#define A_PIPE  (NBUF * A_STAGE)      // 98304
#define B_RES   A_PIPE                // B resident: 16 stages x 4K (fp16)
#define SMEM_DYN (A_PIPE + 16 * 4096) // 163840 = 160 KB, 1 CTA/SM

#define NCTA    128                   // one n-tile (N=32) per CTA, M=128
#define NTHREADS 512                  // 16 warps = 4 m-warps x 4 kq-groups
#define CREG    18432u                // combine region stride (128*36*4)

// Device scratch (allocation-free). fp16 bits stored as ushort.
__device__ unsigned short g_WcT[4 * D_ * D_];     // combined W^T fp16 [n][k]
__device__ unsigned short g_W1T[4 * D_ * D_];     // step-1 W^T fp16
__device__ unsigned short g_hHi[2][B_ * D_];      // h fp16-hi ping-pong
__device__ unsigned short g_hLo[2][B_ * D_];      // h fp16-lo ping-pong
__device__ unsigned       g_bar;                  // grid barrier counter

// ---------------------------------------------------------------------------
// PTX helpers (plain sm_80+ features only)
// ---------------------------------------------------------------------------
__device__ __forceinline__ uint32_t s2u(const void* p) {
    uint32_t a;
    asm("{ .reg .u64 t; cvta.to.shared.u64 t, %1; cvt.u32.u64 %0, t; }"
        : "=r"(a) : "l"(p));
    return a;
}
__device__ __forceinline__ void cpasync16(uint32_t dst, const void* src) {
    asm volatile("cp.async.cg.shared.global [%0], [%1], 16;" :: "r"(dst), "l"(src));
}
__device__ __forceinline__ void cp_commit() {
    asm volatile("cp.async.commit_group;" ::: "memory");
}
template <int N> __device__ __forceinline__ void cp_wait() {
    asm volatile("cp.async.wait_group %0;" :: "n"(N) : "memory");
}
__device__ __forceinline__ void ldsm4(uint32_t* r, uint32_t addr) {
    asm volatile("ldmatrix.sync.aligned.m8n8.x4.shared.b16 {%0,%1,%2,%3}, [%4];"
        : "=r"(r[0]), "=r"(r[1]), "=r"(r[2]), "=r"(r[3]) : "r"(addr));
}
__device__ __forceinline__ void mma_f16(float* c, const uint32_t* a,
                                        uint32_t b0, uint32_t b1) {
    asm volatile("mma.sync.aligned.m16n8k16.row.col.f32.f16.f16.f32 "
        "{%0,%1,%2,%3}, {%4,%5,%6,%7}, {%8,%9}, {%0,%1,%2,%3};"
        : "+f"(c[0]), "+f"(c[1]), "+f"(c[2]), "+f"(c[3])
        : "r"(a[0]), "r"(a[1]), "r"(a[2]), "r"(a[3]), "r"(b0), "r"(b1));
}
__device__ __forceinline__ uint32_t sw128(uint32_t off) {
    return off ^ ((off >> 3) & 0x70);
}

// ---------------------------------------------------------------------------
// Merged prologue: weights transform (fp16) + x0 split + barrier reset.
// ---------------------------------------------------------------------------
__global__ void prep_all(const float* __restrict__ Wk,
                         const float* __restrict__ Wr,
                         const float* __restrict__ x,
                         float* __restrict__ out) {
    int i = blockIdx.x * blockDim.x + threadIdx.x;
    {   // ---- weights: [n][k] transposed, gates {Wz+Rz, Wr+Rr, Wh, Rh} ----
        int n  = i >> 7;
        int k0 = (i & 127) * 8;
        int d = n >> 2, g = n & 3;
        long o = (long)n * D_ + k0;
        #pragma unroll
        for (int j = 0; j < 8; j++) {
            long src = (long)(k0 + j) * (3 * D_) + (long)g * D_ + d;
            float wc, w1;
            if (g == 3) {
                float rh = Wr[(long)(k0 + j) * (3 * D_) + 2 * D_ + d];
                wc = rh; w1 = 0.f;
            } else {
                float a = Wk[src];
                float b = Wr[src];
                w1 = a;
                wc = (g == 2) ? a : (a + b);
            }
            g_WcT[o + j] = __half_as_ushort(__float2half_rn(wc));
            g_W1T[o + j] = __half_as_ushort(__float2half_rn(w1));
        }
    }
    if (i < B_ * D_) {   // ---- x0: out[:,0,:] = x0; split into h buf 0 ----
        if (i == 0) g_bar = 0u;
        int b = i >> 10, d = i & (D_ - 1);
        float v = x[(long)b * D_ + d];
        out[(long)b * (T_ * D_) + d] = v;
        __half hi = __float2half_rn(v);
        g_hHi[0][i] = __half_as_ushort(hi);
        g_hLo[0][i] = __half_as_ushort(__float2half_rn(v - __half2float(hi)));
    }
}

// ---------------------------------------------------------------------------
// Loaders (512 threads, coalesced — R13 style)
// ---------------------------------------------------------------------------
__device__ __forceinline__ void load_A(
    uint32_t st, int k0,
    const unsigned short* Ahi, const unsigned short* Alo, int tid)
{
    #pragma unroll
    for (int t = 0; t < 2; t++) {
        int r   = t * 512 + tid;            // 1024 chunks per 16KB half
        int row = r >> 3, ch = r & 7;
        uint32_t sw = sw128((uint32_t)(row * 128 + ch * 16));
        const long ko = (long)k0 + ch * 8;
        cpasync16(st +         sw, Ahi + (long)row * D_ + ko);
        cpasync16(st + 16384 + sw, Alo + (long)row * D_ + ko);
    }
}
// B resident (fp16 single): 16 stages x 32 rows x 64 k = 64 KB.
__device__ __forceinline__ void load_B_res(
    uint32_t sbase, const unsigned short* Bw, int nrow0, int tid)
{
    #pragma unroll
    for (int t = 0; t < 8; t++) {
        int r   = t * 512 + tid;            // 4096 chunks total
        int s   = r >> 8;                   // stage
        int rr  = r & 255;
        int row = rr >> 3, ch = rr & 7;
        uint32_t dst = sbase + B_RES + (uint32_t)s * 4096;
        uint32_t sw = sw128((uint32_t)(row * 128 + ch * 16));
        const long ko = (long)s * KSTAGE + ch * 8;
        cpasync16(dst + sw, Bw + (long)(nrow0 + row) * D_ + ko);
    }
}

// ---------------------------------------------------------------------------
// Persistent GRU: 255 steps, grid barrier between steps.
// Grid 128 CTAs (1/SM): CTA tile M=128 x N=32; fp16 weights RESIDENT in
// smem (single-term). A = h split into fp16 hi/lo; GEMM = 2 MMAs per tile
// (Ah*B + Al*B). 16 warps = 4 m-warps x 4 kq-groups, warp tile 32x32;
// 3-buffer A pipeline (depth-2 refill); distributed combine + epilogue.
// ---------------------------------------------------------------------------
extern __shared__ char dsm[];

__global__ __launch_bounds__(NTHREADS, 1)
void gru_persist(const unsigned short* __restrict__ WcT,
                 const unsigned short* __restrict__ W1T,
                 const float* __restrict__ bias,
                 float* __restrict__ out,
                 unsigned short* __restrict__ hHi,
                 unsigned short* __restrict__ hLo)
{
    const uint32_t sbase = s2u(dsm);
    const int tid  = threadIdx.x;
    const int wid  = tid >> 5, lane = tid & 31;
    const int wk   = wid >> 2;                      // kq-group 0..3
    const int wm   = wid & 3;                       // m-warp (32 rows each)
    const int nb   = blockIdx.x;                    // n-tile (N=32)
    const int nrow0 = nb * 32;

    // per-lane ldmatrix geometry
    const int fr   = (lane & 7) + ((lane >> 3) & 1) * 8;
    const int fch  = (lane >> 4) * 16;
    const uint32_t swz = (uint32_t)(lane & 7) << 4;
    const uint32_t ckq = (uint32_t)(wk * 32 + fch);   // this group's k-quarter

    // distributed-epilogue coordinates: each thread owns (erow, d2..d2+1)
    const int erow = tid >> 2;                      // 0..127
    const int ed0  = (tid & 3) * 2;                 // local d: ed0, ed0+1
    const int dg0  = nb * 8 + ed0;                  // global d base

    float bzv[2], brv[2], bhv[2];
    #pragma unroll
    for (int q = 0; q < 2; q++) {
        bzv[q] = bias[dg0 + q];
        brv[q] = bias[D_ + dg0 + q];
        bhv[q] = bias[2 * D_ + dg0 + q];
    }

    // ---- prime for t = 1: B-resident = W1, A stages 0..1 ----
    const unsigned short* Ahi = hHi;
    const unsigned short* Alo = hLo;
    load_B_res(sbase, W1T, nrow0, tid);
    cp_commit();
    load_A(sbase,           0,      Ahi, Alo, tid); cp_commit();
    load_A(sbase + A_STAGE, KSTAGE, Ahi, Alo, tid); cp_commit();

    float hold[2] = {0.f, 0.f};                     // h0 = 0

    for (int t = 1; t < T_; t++) {
        const bool last = (t == T_ - 1);

        float acc[2][4][4];
        #pragma unroll
        for (int i = 0; i < 2; i++)
            #pragma unroll
            for (int j = 0; j < 4; j++)
                #pragma unroll
                for (int q = 0; q < 4; q++) acc[i][j][q] = 0.f;

        int buf = 0;
        for (int s = 0; s < NSTAGES; s++) {
            if (s < NSTAGES - 1) cp_wait<1>();
            else                 cp_wait<0>();
            __syncthreads();

            // refill stage s+2 into buf (s+2)%3 — freed at stage s-1
            if (s + 2 < NSTAGES) {
                int nxt = buf + 2; if (nxt >= NBUF) nxt -= NBUF;
                load_A(sbase + (uint32_t)nxt * A_STAGE, (s + 2) * KSTAGE,
                       Ahi, Alo, tid);
                cp_commit();
            }

            const uint32_t aHi = sbase + (uint32_t)buf * A_STAGE;
            const uint32_t aLo = aHi + 16384;
            const uint32_t bB  = sbase + B_RES + (uint32_t)s * 4096;

            const uint32_t c = ckq ^ swz;
            uint32_t ah[2][4], al[2][4], bb[2][4];
            #pragma unroll
            for (int mt = 0; mt < 2; mt++) {
                uint32_t ro = (uint32_t)((wm * 32 + mt * 16 + fr) * 128) + c;
                ldsm4(ah[mt], aHi + ro);
                ldsm4(al[mt], aLo + ro);
            }
            #pragma unroll
            for (int np = 0; np < 2; np++) {
                uint32_t ro = (uint32_t)((np * 16 + fr) * 128) + c;
                ldsm4(bb[np], bB + ro);
            }
            #pragma unroll
            for (int mt = 0; mt < 2; mt++)
                #pragma unroll
                for (int nt = 0; nt < 4; nt++) {
                    const int np = nt >> 1, j = nt & 1;
                    mma_f16(acc[mt][nt], ah[mt], bb[np][j], bb[np][j + 2]);
                    mma_f16(acc[mt][nt], al[mt], bb[np][j], bb[np][j + 2]);
                }
            buf = buf + 1; if (buf == NBUF) buf = 0;
        }

        // -------- all groups dump partials to smem (A-pipe area idle) -----
        __syncthreads();                       // all warps done reading bufs
        {
            const uint32_t comb = sbase + (uint32_t)wk * CREG;
            #pragma unroll
            for (int mt = 0; mt < 2; mt++)
                #pragma unroll
                for (int nt = 0; nt < 4; nt++) {
                    int r0 = wm * 32 + mt * 16 + (lane >> 2);
                    int c0 = nt * 8 + 2 * (lane & 3);
                    uint32_t ad = comb + (uint32_t)((r0 * 36 + c0) << 2);
                    asm volatile("st.shared.v2.f32 [%0], {%1,%2};"
                                 :: "r"(ad), "f"(acc[mt][nt][0]), "f"(acc[mt][nt][1]));
                    asm volatile("st.shared.v2.f32 [%0], {%1,%2};"
                                 :: "r"(ad + 8 * 36 * 4),
                                    "f"(acc[mt][nt][2]), "f"(acc[mt][nt][3]));
                }
        }
        __syncthreads();

        // -------- distributed combine + GRU gates: 2 outputs / thread -----
        unsigned short* nhi = hHi + (size_t)(t & 1) * B_ * D_;
        unsigned short* nlo = hLo + (size_t)(t & 1) * B_ * D_;
        {
            float hv[2];
            #pragma unroll
            for (int q = 0; q < 2; q++) {
                const int dl = ed0 + q;
                const uint32_t off = (uint32_t)((erow * 36 + dl * 4) << 2);
                float az = 0.f, ar = 0.f, ahs = 0.f, ags = 0.f;
                #pragma unroll
                for (int gq = 0; gq < 4; gq++) {
                    float p0, p1, p2, p3;
                    asm volatile("ld.shared.v4.f32 {%0,%1,%2,%3}, [%4];"
                                 : "=f"(p0), "=f"(p1), "=f"(p2), "=f"(p3)
                                 : "r"(sbase + (uint32_t)gq * CREG + off));
                    az += p0; ar += p1; ahs += p2; ags += p3;
                }
                float z  = 1.f / (1.f + __expf(-(az + bzv[q])));
                float rr = 1.f / (1.f + __expf(-(ar + brv[q])));
                float xc = ahs + bhv[q] + rr * ags;
                float e  = __expf(-2.f * xc);
                float cand = (1.f - e) / (1.f + e);
                float h = z * hold[q] + (1.f - z) * cand;
                hold[q] = h;
                hv[q] = h;
            }
            // coalesced stores
            float* po = out + (long)erow * (T_ * D_) + (long)t * D_ + dg0;
            *(float2*)po = make_float2(hv[0], hv[1]);
            __half h0 = __float2half_rn(hv[0]);
            __half h1 = __float2half_rn(hv[1]);
            uint32_t hiw = (uint32_t)__half_as_ushort(h0)
                         | ((uint32_t)__half_as_ushort(h1) << 16);
            __half l0 = __float2half_rn(hv[0] - __half2float(h0));
            __half l1 = __float2half_rn(hv[1] - __half2float(h1));
            uint32_t low = (uint32_t)__half_as_ushort(l0)
                         | ((uint32_t)__half_as_ushort(l1) << 16);
            *(uint32_t*)(nhi + (long)erow * D_ + dg0) = hiw;
            *(uint32_t*)(nlo + (long)erow * D_ + dg0) = low;
        }

        if (!last) {
            // ---- grid barrier: all h_t writes visible before step t+1 ----
            __threadfence();
            __syncthreads();
            if (tid == 0) {
                atomicAdd(&g_bar, 1u);
                volatile unsigned* vb = &g_bar;
                const unsigned target = (unsigned)NCTA * (unsigned)t;
                while (*vb < target) { }
            }
            __syncthreads();
            __threadfence();

            Ahi = nhi; Alo = nlo;

            // switch resident weights to Wc after step 1
            if (t == 1) {
                load_B_res(sbase, WcT, nrow0, tid);
                cp_commit();
            }
            // A stages 0..1 for next step
            load_A(sbase,           0,      Ahi, Alo, tid); cp_commit();
            load_A(sbase + A_STAGE, KSTAGE, Ahi, Alo, tid); cp_commit();
        }
    }
}

// ---------------------------------------------------------------------------
extern "C" void kernel_launch(void* const* d_in, const int* in_sizes, int n_in,
                              void* d_out, int out_size) {
    const float* x    = (const float*)d_in[0];
    const float* Wk   = (const float*)d_in[1];
    const float* Wr   = (const float*)d_in[2];
    const float* bias = (const float*)d_in[3];
    float* out = (float*)d_out;

    unsigned short *WcT, *W1T, *hHi, *hLo;
    cudaGetSymbolAddress((void**)&WcT, g_WcT);
    cudaGetSymbolAddress((void**)&W1T, g_W1T);
    cudaGetSymbolAddress((void**)&hHi, g_hHi);
    cudaGetSymbolAddress((void**)&hLo, g_hLo);

    cudaFuncSetAttribute(gru_persist,
                         cudaFuncAttributeMaxDynamicSharedMemorySize, SMEM_DYN);

    prep_all<<<2048, 256>>>(Wk, Wr, x, out);   // also resets g_bar

    gru_persist<<<NCTA, NTHREADS, SMEM_DYN>>>(WcT, W1T, bias, out, hHi, hLo);
}

// round 16
// speedup vs baseline: 1.9447x; 1.5233x over previous
#include <cuda_runtime.h>
#include <cuda_fp16.h>
#include <math.h>
#include <stdint.h>

// Shapes (fixed)
#define D_  1024
#define B_  128
#define T_  256

#define KSTAGE  128                   // k per stage (2 x 64k sub-tiles)
#define NSTAGES (D_ / KSTAGE)         // 8
#define A_STAGE 32768                 // A: 128 rows x 128 k fp16 (2 sub-tiles)
#define NBUF    3
#define A_PIPE  (NBUF * A_STAGE)      // 98304
#define B_RES   A_PIPE                // B resident: 16 sub-tiles x 4KB
#define SMEM_DYN (A_PIPE + 16 * 4096) // 163840 = 160 KB, 1 CTA/SM

#define NCTA    128                   // one n-tile (N=32) per CTA, M=128
#define NTHREADS 512                  // 16 warps = 4 m-warps x 4 kq-groups
#define CREG    18432u                // combine region stride (128*36*4)

// Device scratch (allocation-free). fp16 bits stored as ushort.
__device__ unsigned short g_WcT[4 * D_ * D_];     // combined W^T fp16 [n][k]
__device__ unsigned short g_W1T[4 * D_ * D_];     // step-1 W^T fp16
__device__ unsigned short g_hF[2][B_ * D_];       // h fp16 ping-pong
__device__ unsigned       g_bar;                  // grid barrier counter

// ---------------------------------------------------------------------------
// PTX helpers (plain sm_80+ features only)
// ---------------------------------------------------------------------------
__device__ __forceinline__ uint32_t s2u(const void* p) {
    uint32_t a;
    asm("{ .reg .u64 t; cvta.to.shared.u64 t, %1; cvt.u32.u64 %0, t; }"
        : "=r"(a) : "l"(p));
    return a;
}
__device__ __forceinline__ void cpasync16(uint32_t dst, const void* src) {
    asm volatile("cp.async.cg.shared.global [%0], [%1], 16;" :: "r"(dst), "l"(src));
}
__device__ __forceinline__ void cp_commit() {
    asm volatile("cp.async.commit_group;" ::: "memory");
}
template <int N> __device__ __forceinline__ void cp_wait() {
    asm volatile("cp.async.wait_group %0;" :: "n"(N) : "memory");
}
__device__ __forceinline__ void ldsm4(uint32_t* r, uint32_t addr) {
    asm volatile("ldmatrix.sync.aligned.m8n8.x4.shared.b16 {%0,%1,%2,%3}, [%4];"
        : "=r"(r[0]), "=r"(r[1]), "=r"(r[2]), "=r"(r[3]) : "r"(addr));
}
__device__ __forceinline__ void mma_f16(float* c, const uint32_t* a,
                                        uint32_t b0, uint32_t b1) {
    asm volatile("mma.sync.aligned.m16n8k16.row.col.f32.f16.f16.f32 "
        "{%0,%1,%2,%3}, {%4,%5,%6,%7}, {%8,%9}, {%0,%1,%2,%3};"
        : "+f"(c[0]), "+f"(c[1]), "+f"(c[2]), "+f"(c[3])
        : "r"(a[0]), "r"(a[1]), "r"(a[2]), "r"(a[3]), "r"(b0), "r"(b1));
}
__device__ __forceinline__ uint32_t sw128(uint32_t off) {
    return off ^ ((off >> 3) & 0x70);
}

// ---------------------------------------------------------------------------
// Merged prologue: weights transform (fp16) + x0 + barrier reset.
// ---------------------------------------------------------------------------
__global__ void prep_all(const float* __restrict__ Wk,
                         const float* __restrict__ Wr,
                         const float* __restrict__ x,
                         float* __restrict__ out) {
    int i = blockIdx.x * blockDim.x + threadIdx.x;
    {   // ---- weights: [n][k] transposed, gates {Wz+Rz, Wr+Rr, Wh, Rh} ----
        int n  = i >> 7;
        int k0 = (i & 127) * 8;
        int d = n >> 2, g = n & 3;
        long o = (long)n * D_ + k0;
        #pragma unroll
        for (int j = 0; j < 8; j++) {
            long src = (long)(k0 + j) * (3 * D_) + (long)g * D_ + d;
            float wc, w1;
            if (g == 3) {
                float rh = Wr[(long)(k0 + j) * (3 * D_) + 2 * D_ + d];
                wc = rh; w1 = 0.f;
            } else {
                float a = Wk[src];
                float b = Wr[src];
                w1 = a;
                wc = (g == 2) ? a : (a + b);
            }
            g_WcT[o + j] = __half_as_ushort(__float2half_rn(wc));
            g_W1T[o + j] = __half_as_ushort(__float2half_rn(w1));
        }
    }
    if (i < B_ * D_) {   // ---- x0: out[:,0,:] = x0; fp16 into h buf 0 ----
        if (i == 0) g_bar = 0u;
        int b = i >> 10, d = i & (D_ - 1);
        float v = x[(long)b * D_ + d];
        out[(long)b * (T_ * D_) + d] = v;
        g_hF[0][i] = __half_as_ushort(__float2half_rn(v));
    }
}

// ---------------------------------------------------------------------------
// Loaders (512 threads, coalesced)
// ---------------------------------------------------------------------------
// A stage: 2 sub-tiles x (128 rows x 64 k fp16, 128B rows) = 32 KB.
__device__ __forceinline__ void load_A(
    uint32_t st, int k0, const unsigned short* Ah, int tid)
{
    #pragma unroll
    for (int t = 0; t < 4; t++) {
        int r   = t * 512 + tid;            // 0..2047 16B-chunks
        int sub = r >> 10;                  // sub-tile 0/1
        int rr  = r & 1023;
        int row = rr >> 3, ch = rr & 7;
        uint32_t sw = sw128((uint32_t)(row * 128 + ch * 16));
        const long ko = (long)k0 + sub * 64 + ch * 8;
        cpasync16(st + (uint32_t)sub * 16384 + sw, Ah + (long)row * D_ + ko);
    }
}
// B resident (fp16): 16 sub-tiles x (32 rows x 64 k) = 64 KB.
__device__ __forceinline__ void load_B_res(
    uint32_t sbase, const unsigned short* Bw, int nrow0, int tid)
{
    #pragma unroll
    for (int t = 0; t < 8; t++) {
        int r   = t * 512 + tid;            // 4096 chunks total
        int s   = r >> 8;                   // sub-tile
        int rr  = r & 255;
        int row = rr >> 3, ch = rr & 7;
        uint32_t dst = sbase + B_RES + (uint32_t)s * 4096;
        uint32_t sw = sw128((uint32_t)(row * 128 + ch * 16));
        const long ko = (long)s * 64 + ch * 8;
        cpasync16(dst + sw, Bw + (long)(nrow0 + row) * D_ + ko);
    }
}

// ---------------------------------------------------------------------------
// Persistent GRU: 255 steps, grid barrier between steps.
// Grid 128 CTAs (1/SM): CTA tile M=128 x N=32; fp16 weights RESIDENT (64KB).
// A = fp16(h), single term -> 1 MMA per (tile, k16). 16 warps = 4 m-warps x
// 4 kq-groups; stage k=128 (2 sub-tiles), 8 stages/step; 3-buffer pipeline;
// distributed combine + epilogue; register-carried h_old.
// ---------------------------------------------------------------------------
extern __shared__ char dsm[];

__global__ __launch_bounds__(NTHREADS, 1)
void gru_persist(const unsigned short* __restrict__ WcT,
                 const unsigned short* __restrict__ W1T,
                 const float* __restrict__ bias,
                 float* __restrict__ out,
                 unsigned short* __restrict__ hF)
{
    const uint32_t sbase = s2u(dsm);
    const int tid  = threadIdx.x;
    const int wid  = tid >> 5, lane = tid & 31;
    const int wk   = wid >> 2;                      // kq-group 0..3
    const int wm   = wid & 3;                       // m-warp (32 rows each)
    const int nb   = blockIdx.x;                    // n-tile (N=32)
    const int nrow0 = nb * 32;

    // per-lane ldmatrix geometry
    const int fr   = (lane & 7) + ((lane >> 3) & 1) * 8;
    const int fch  = (lane >> 4) * 16;
    const uint32_t swz = (uint32_t)(lane & 7) << 4;
    const int subk = wk >> 1;                       // sub-tile within stage
    const int kc0  = (wk & 1) * 2;                  // first k16 chunk in sub

    // distributed-epilogue coordinates: each thread owns (erow, d2..d2+1)
    const int erow = tid >> 2;                      // 0..127
    const int ed0  = (tid & 3) * 2;                 // local d: ed0, ed0+1
    const int dg0  = nb * 8 + ed0;                  // global d base

    float bzv[2], brv[2], bhv[2];
    #pragma unroll
    for (int q = 0; q < 2; q++) {
        bzv[q] = bias[dg0 + q];
        brv[q] = bias[D_ + dg0 + q];
        bhv[q] = bias[2 * D_ + dg0 + q];
    }

    // ---- prime for t = 1: B-resident = W1, A stages 0..1 ----
    const unsigned short* Ah = hF;
    load_B_res(sbase, W1T, nrow0, tid);
    cp_commit();
    load_A(sbase,           0,      Ah, tid); cp_commit();
    load_A(sbase + A_STAGE, KSTAGE, Ah, tid); cp_commit();

    float hold[2] = {0.f, 0.f};                     // h0 = 0

    for (int t = 1; t < T_; t++) {
        const bool last = (t == T_ - 1);

        float acc[2][4][4];
        #pragma unroll
        for (int i = 0; i < 2; i++)
            #pragma unroll
            for (int j = 0; j < 4; j++)
                #pragma unroll
                for (int q = 0; q < 4; q++) acc[i][j][q] = 0.f;

        int buf = 0;
        for (int s = 0; s < NSTAGES; s++) {
            if (s < NSTAGES - 1) cp_wait<1>();
            else                 cp_wait<0>();
            __syncthreads();

            // refill stage s+2 into buf (s+2)%3 — freed at stage s-1
            if (s + 2 < NSTAGES) {
                int nxt = buf + 2; if (nxt >= NBUF) nxt -= NBUF;
                load_A(sbase + (uint32_t)nxt * A_STAGE, (s + 2) * KSTAGE,
                       Ah, tid);
                cp_commit();
            }

            const uint32_t aT = sbase + (uint32_t)buf * A_STAGE
                              + (uint32_t)subk * 16384;
            const uint32_t bT = sbase + B_RES
                              + (uint32_t)(s * 2 + subk) * 4096;

            #pragma unroll
            for (int kc = 0; kc < 2; kc++) {
                const uint32_t c = (uint32_t)((kc0 + kc) * 32 + fch) ^ swz;
                uint32_t ah[2][4], bb[2][4];
                #pragma unroll
                for (int mt = 0; mt < 2; mt++) {
                    uint32_t ro = (uint32_t)((wm * 32 + mt * 16 + fr) * 128) + c;
                    ldsm4(ah[mt], aT + ro);
                }
                #pragma unroll
                for (int np = 0; np < 2; np++) {
                    uint32_t ro = (uint32_t)((np * 16 + fr) * 128) + c;
                    ldsm4(bb[np], bT + ro);
                }
                #pragma unroll
                for (int mt = 0; mt < 2; mt++)
                    #pragma unroll
                    for (int nt = 0; nt < 4; nt++) {
                        const int np = nt >> 1, j = nt & 1;
                        mma_f16(acc[mt][nt], ah[mt], bb[np][j], bb[np][j + 2]);
                    }
            }
            buf = buf + 1; if (buf == NBUF) buf = 0;
        }

        // -------- all groups dump partials to smem (A-pipe area idle) -----
        __syncthreads();                       // all warps done reading bufs
        {
            const uint32_t comb = sbase + (uint32_t)wk * CREG;
            #pragma unroll
            for (int mt = 0; mt < 2; mt++)
                #pragma unroll
                for (int nt = 0; nt < 4; nt++) {
                    int r0 = wm * 32 + mt * 16 + (lane >> 2);
                    int c0 = nt * 8 + 2 * (lane & 3);
                    uint32_t ad = comb + (uint32_t)((r0 * 36 + c0) << 2);
                    asm volatile("st.shared.v2.f32 [%0], {%1,%2};"
                                 :: "r"(ad), "f"(acc[mt][nt][0]), "f"(acc[mt][nt][1]));
                    asm volatile("st.shared.v2.f32 [%0], {%1,%2};"
                                 :: "r"(ad + 8 * 36 * 4),
                                    "f"(acc[mt][nt][2]), "f"(acc[mt][nt][3]));
                }
        }
        __syncthreads();

        // -------- distributed combine + GRU gates: 2 outputs / thread -----
        unsigned short* nh = hF + (size_t)(t & 1) * B_ * D_;
        {
            float hv[2];
            #pragma unroll
            for (int q = 0; q < 2; q++) {
                const int dl = ed0 + q;
                const uint32_t off = (uint32_t)((erow * 36 + dl * 4) << 2);
                float az = 0.f, ar = 0.f, ahs = 0.f, ags = 0.f;
                #pragma unroll
                for (int gq = 0; gq < 4; gq++) {
                    float p0, p1, p2, p3;
                    asm volatile("ld.shared.v4.f32 {%0,%1,%2,%3}, [%4];"
                                 : "=f"(p0), "=f"(p1), "=f"(p2), "=f"(p3)
                                 : "r"(sbase + (uint32_t)gq * CREG + off));
                    az += p0; ar += p1; ahs += p2; ags += p3;
                }
                float z  = 1.f / (1.f + __expf(-(az + bzv[q])));
                float rr = 1.f / (1.f + __expf(-(ar + brv[q])));
                float xc = ahs + bhv[q] + rr * ags;
                float e  = __expf(-2.f * xc);
                float cand = (1.f - e) / (1.f + e);
                float h = z * hold[q] + (1.f - z) * cand;
                hold[q] = h;
                hv[q] = h;
            }
            // coalesced stores
            float* po = out + (long)erow * (T_ * D_) + (long)t * D_ + dg0;
            *(float2*)po = make_float2(hv[0], hv[1]);
            uint32_t hw = (uint32_t)__half_as_ushort(__float2half_rn(hv[0]))
                        | ((uint32_t)__half_as_ushort(__float2half_rn(hv[1])) << 16);
            *(uint32_t*)(nh + (long)erow * D_ + dg0) = hw;
        }

        if (!last) {
            // ---- grid barrier: all h_t writes visible before step t+1 ----
            __threadfence();
            __syncthreads();
            if (tid == 0) {
                atomicAdd(&g_bar, 1u);
                volatile unsigned* vb = &g_bar;
                const unsigned target = (unsigned)NCTA * (unsigned)t;
                while (*vb < target) { }
            }
            __syncthreads();
            __threadfence();

            Ah = nh;

            // switch resident weights to Wc after step 1
            if (t == 1) {
                load_B_res(sbase, WcT, nrow0, tid);
                cp_commit();
            }
            // A stages 0..1 for next step
            load_A(sbase,           0,      Ah, tid); cp_commit();
            load_A(sbase + A_STAGE, KSTAGE, Ah, tid); cp_commit();
        }
    }
}

// ---------------------------------------------------------------------------
extern "C" void kernel_launch(void* const* d_in, const int* in_sizes, int n_in,
                              void* d_out, int out_size) {
    const float* x    = (const float*)d_in[0];
    const float* Wk   = (const float*)d_in[1];
    const float* Wr   = (const float*)d_in[2];
    const float* bias = (const float*)d_in[3];
    float* out = (float*)d_out;

    unsigned short *WcT, *W1T, *hF;
    cudaGetSymbolAddress((void**)&WcT, g_WcT);
    cudaGetSymbolAddress((void**)&W1T, g_W1T);
    cudaGetSymbolAddress((void**)&hF,  g_hF);

    cudaFuncSetAttribute(gru_persist,
                         cudaFuncAttributeMaxDynamicSharedMemorySize, SMEM_DYN);

    prep_all<<<2048, 256>>>(Wk, Wr, x, out);   // also resets g_bar

    gru_persist<<<NCTA, NTHREADS, SMEM_DYN>>>(WcT, W1T, bias, out, hF);
}